// round 1
// baseline (speedup 1.0000x reference)
#include <cuda_runtime.h>
#include <cuda_bf16.h>
#include <math.h>

#define B_   16
#define G_   2048
#define D_   256
#define H_   8
#define DH_  32
#define FFN_ 1024
#define L_   4
#define CH_  64
#define NC_  (G_ / CH_)           // 32 chunks
#define BG_  (B_ * G_)            // 32768 rows
#define BH_  (B_ * H_)            // 128

// ---------------- scratch (device globals; no runtime allocation) ----------
__device__ float g_h[(size_t)BG_ * D_];
__device__ float g_hn[(size_t)BG_ * D_];
__device__ float g_q[(size_t)BG_ * D_];
__device__ float g_k[(size_t)BG_ * D_];
__device__ float g_v[(size_t)BG_ * D_];
__device__ float g_mid[(size_t)BG_ * FFN_];
__device__ float g_ckv[(size_t)BH_ * NC_ * DH_ * DH_];   // per-chunk K^T V, then exclusive prefix
__device__ float g_cks[(size_t)BH_ * NC_ * DH_];         // per-chunk sum k, then exclusive prefix

// ---------------- embedding: h = gene_emb + REE(x) -------------------------
__global__ void embed_kernel(const float* __restrict__ x,
                             const float* __restrict__ ge,
                             const float* __restrict__ invf,
                             float* __restrict__ h) {
    size_t idx = (size_t)blockIdx.x * 256 + threadIdx.x;   // over BG_*D_
    int d = (int)(idx & (D_ - 1));
    size_t bg = idx >> 8;
    int g = (int)(bg & (G_ - 1));
    float xv = x[bg];
    float e;
    if (d < D_ / 2) e = sinf(xv * invf[d]);
    else            e = cosf(xv * invf[d - D_ / 2]);
    if (xv == -10.0f) e = 0.0f;
    h[idx] = ge[(size_t)g * D_ + d] + e;
}

// ---------------- layernorm (warp per row, D=256) ---------------------------
__global__ void ln_kernel(const float* __restrict__ x,
                          const float* __restrict__ gam,
                          const float* __restrict__ bet,
                          float* __restrict__ out) {
    int warp = threadIdx.x >> 5, lane = threadIdx.x & 31;
    int row = blockIdx.x * 8 + warp;
    const float* xr = x + (size_t)row * D_;
    float vals[8];
    float s = 0.f;
#pragma unroll
    for (int i = 0; i < 8; i++) { vals[i] = xr[lane + i * 32]; s += vals[i]; }
#pragma unroll
    for (int o = 16; o; o >>= 1) s += __shfl_xor_sync(0xffffffffu, s, o);
    float mean = s * (1.0f / D_);
    float vs = 0.f;
#pragma unroll
    for (int i = 0; i < 8; i++) { float dlt = vals[i] - mean; vs += dlt * dlt; }
#pragma unroll
    for (int o = 16; o; o >>= 1) vs += __shfl_xor_sync(0xffffffffu, vs, o);
    float rstd = rsqrtf(vs * (1.0f / D_) + 1e-5f);
    float* orow = out + (size_t)row * D_;
#pragma unroll
    for (int i = 0; i < 8; i++) {
        int c = lane + i * 32;
        orow[c] = (vals[i] - mean) * rstd * gam[c] + bet[c];
    }
}

// ---------------- SGEMM 128x128x8, 256 threads, 8x8/thread ------------------
// EPI: 0 = +bias, 1 = (x+bias)^2, 2 = gelu_exact(x+bias), 3 = C += x+bias
template <int EPI>
__global__ __launch_bounds__(256)
void sgemm_kernel(const float* __restrict__ A, const float* __restrict__ Bm,
                  const float* __restrict__ bias, float* __restrict__ C,
                  int M, int N, int K) {
    __shared__ float As[8][128];
    __shared__ float Bs[8][128];
    int t = threadIdx.x;
    int m0 = blockIdx.y * 128;
    int n0 = blockIdx.x * 128;
    int aRow = t >> 1;
    int aCol = (t & 1) * 4;
    int bRow = t >> 5;
    int bCol = (t & 31) * 4;
    int tr = (t >> 4) * 8;
    int tc = (t & 15) * 8;
    float acc[8][8];
#pragma unroll
    for (int i = 0; i < 8; i++)
#pragma unroll
        for (int j = 0; j < 8; j++) acc[i][j] = 0.f;

    const float* Aptr = A + (size_t)m0 * K;
    const float* Bptr = Bm + n0;
    for (int k0 = 0; k0 < K; k0 += 8) {
        float4 av = *(const float4*)(Aptr + (size_t)aRow * K + k0 + aCol);
        As[aCol + 0][aRow] = av.x; As[aCol + 1][aRow] = av.y;
        As[aCol + 2][aRow] = av.z; As[aCol + 3][aRow] = av.w;
        float4 bv = *(const float4*)(Bptr + (size_t)(k0 + bRow) * N + bCol);
        *(float4*)&Bs[bRow][bCol] = bv;
        __syncthreads();
#pragma unroll
        for (int kk = 0; kk < 8; kk++) {
            float ra[8], rb[8];
#pragma unroll
            for (int i = 0; i < 8; i++) ra[i] = As[kk][tr + i];
#pragma unroll
            for (int j = 0; j < 8; j++) rb[j] = Bs[kk][tc + j];
#pragma unroll
            for (int i = 0; i < 8; i++)
#pragma unroll
                for (int j = 0; j < 8; j++)
                    acc[i][j] = fmaf(ra[i], rb[j], acc[i][j]);
        }
        __syncthreads();
    }
#pragma unroll
    for (int i = 0; i < 8; i++) {
        size_t row = (size_t)(m0 + tr + i);
#pragma unroll
        for (int j = 0; j < 8; j++) {
            int col = n0 + tc + j;
            float vv = acc[i][j] + bias[col];
            if (EPI == 1) vv = vv * vv;
            else if (EPI == 2) vv = 0.5f * vv * (1.0f + erff(vv * 0.70710678118654752f));
            size_t idx = row * N + col;
            if (EPI == 3) C[idx] += vv;
            else          C[idx] = vv;
        }
    }
}

// ---------------- attention phase 1: per-chunk K^T V and sum(k) -------------
__global__ void attn_p1(const float* __restrict__ k, const float* __restrict__ v,
                        float* __restrict__ ckv, float* __restrict__ cks) {
    __shared__ float Ks[CH_][33], Vs[CH_][33];
    int blk = blockIdx.x;                // bh * NC_ + c
    int c = blk & (NC_ - 1);
    int bh = blk >> 5;
    int b = bh / H_, hh = bh % H_;
    int t = threadIdx.x;
    size_t base = ((size_t)(b * G_ + c * CH_)) * D_ + hh * DH_;
    for (int e = t; e < CH_ * DH_; e += 256) {
        int i = e >> 5, d = e & 31;
        size_t gi = base + (size_t)i * D_ + d;
        Ks[i][d] = k[gi];
        Vs[i][d] = v[gi];
    }
    __syncthreads();
    for (int e = t; e < DH_ * DH_; e += 256) {
        int f = e >> 5, d = e & 31;
        float s = 0.f;
#pragma unroll
        for (int i = 0; i < CH_; i++) s = fmaf(Ks[i][f], Vs[i][d], s);
        ckv[(size_t)blk * (DH_ * DH_) + e] = s;
    }
    if (t < DH_) {
        float s = 0.f;
#pragma unroll
        for (int i = 0; i < CH_; i++) s += Ks[i][t];
        cks[(size_t)blk * DH_ + t] = s;
    }
}

// ---------------- attention phase 2: exclusive prefix across chunks ---------
__global__ void attn_p2(float* __restrict__ ckv, float* __restrict__ cks) {
    int bh = blockIdx.x;
    int t = threadIdx.x;   // 1024 threads
    float run = 0.f;
    for (int c = 0; c < NC_; c++) {
        size_t idx = ((size_t)(bh * NC_ + c)) * (DH_ * DH_) + t;
        float tmp = ckv[idx];
        ckv[idx] = run;
        run += tmp;
    }
    if (t < DH_) {
        float r2 = 0.f;
        for (int c = 0; c < NC_; c++) {
            size_t idx = ((size_t)(bh * NC_ + c)) * DH_ + t;
            float tmp = cks[idx];
            cks[idx] = r2;
            r2 += tmp;
        }
    }
}

// ---------------- attention phase 3: output + residual add into h -----------
__global__ void attn_p3(const float* __restrict__ q, const float* __restrict__ k,
                        const float* __restrict__ v,
                        const float* __restrict__ ckv, const float* __restrict__ cks,
                        float* __restrict__ h) {
    __shared__ float Qs[CH_][33], Ks[CH_][33], Vs[CH_][33];
    __shared__ float S[DH_][33];
    __shared__ float A[CH_][65];
    __shared__ float den[CH_], zz[DH_];
    int blk = blockIdx.x;
    int c = blk & (NC_ - 1);
    int bh = blk >> 5;
    int b = bh / H_, hh = bh % H_;
    int t = threadIdx.x;
    size_t base = ((size_t)(b * G_ + c * CH_)) * D_ + hh * DH_;
    for (int e = t; e < CH_ * DH_; e += 256) {
        int i = e >> 5, d = e & 31;
        size_t gi = base + (size_t)i * D_ + d;
        Qs[i][d] = q[gi];
        Ks[i][d] = k[gi];
        Vs[i][d] = v[gi];
    }
    for (int e = t; e < DH_ * DH_; e += 256)
        S[e >> 5][e & 31] = ckv[(size_t)blk * (DH_ * DH_) + e];
    if (t < DH_) zz[t] = cks[(size_t)blk * DH_ + t];
    __syncthreads();

    // A[i][j] = q_i . k_j   (full; mask applied by loop bounds later)
    for (int e = t; e < CH_ * CH_; e += 256) {
        int i = e >> 6, j = e & 63;
        float s = 0.f;
#pragma unroll
        for (int f = 0; f < DH_; f++) s = fmaf(Qs[i][f], Ks[j][f], s);
        A[i][j] = s;
    }
    __syncthreads();

    // den[i] = q_i . z_prev + sum_{j<=i} A[i][j]
    for (int i = t; i < CH_; i += 256) {
        float s = 0.f;
#pragma unroll
        for (int f = 0; f < DH_; f++) s = fmaf(Qs[i][f], zz[f], s);
        for (int j = 0; j <= i; j++) s += A[i][j];
        den[i] = s;
    }
    __syncthreads();

    // out[i][d] = (q_i . S[:,d] + sum_{j<=i} A[i][j] * V[j][d]) / (den[i]+eps)
    for (int e = t; e < CH_ * DH_; e += 256) {
        int i = e >> 5, d = e & 31;
        float s = 0.f;
#pragma unroll
        for (int f = 0; f < DH_; f++) s = fmaf(Qs[i][f], S[f][d], s);
        for (int j = 0; j <= i; j++) s = fmaf(A[i][j], Vs[j][d], s);
        h[base + (size_t)i * D_ + d] += s / (den[i] + 1e-16f);
    }
}

// ---------------- final projection: out = h @ Wout + bout -------------------
__global__ void out_kernel(const float* __restrict__ h, const float* __restrict__ Wout,
                           const float* __restrict__ bout, float* __restrict__ out) {
    int warp = threadIdx.x >> 5, lane = threadIdx.x & 31;
    int row = blockIdx.x * 8 + warp;
    const float* hr = h + (size_t)row * D_;
    float s = 0.f;
#pragma unroll
    for (int i = 0; i < 8; i++) {
        int c = lane + i * 32;
        s = fmaf(hr[c], Wout[c], s);
    }
#pragma unroll
    for (int o = 16; o; o >>= 1) s += __shfl_xor_sync(0xffffffffu, s, o);
    if (lane == 0) out[row] = s + bout[0];
}

// ---------------------------------------------------------------------------
extern "C" void kernel_launch(void* const* d_in, const int* in_sizes, int n_in,
                              void* d_out, int out_size) {
    const float* x        = (const float*)d_in[0];
    const float* gene_emb = (const float*)d_in[1];
    const float* inv_freq = (const float*)d_in[2];
    const float* Wq       = (const float*)d_in[3];
    const float* bq       = (const float*)d_in[4];
    const float* Wk       = (const float*)d_in[5];
    const float* bk       = (const float*)d_in[6];
    const float* Wv       = (const float*)d_in[7];
    const float* bv       = (const float*)d_in[8];
    const float* ln1_g    = (const float*)d_in[9];
    const float* ln1_b    = (const float*)d_in[10];
    const float* ln2_g    = (const float*)d_in[11];
    const float* ln2_b    = (const float*)d_in[12];
    const float* WU       = (const float*)d_in[13];
    const float* bU       = (const float*)d_in[14];
    const float* WV       = (const float*)d_in[15];
    const float* bV       = (const float*)d_in[16];
    const float* Wout     = (const float*)d_in[17];
    const float* bout     = (const float*)d_in[18];
    float* out = (float*)d_out;

    float *h, *hn, *q, *k, *v, *mid, *ckv, *cks;
    cudaGetSymbolAddress((void**)&h,   g_h);
    cudaGetSymbolAddress((void**)&hn,  g_hn);
    cudaGetSymbolAddress((void**)&q,   g_q);
    cudaGetSymbolAddress((void**)&k,   g_k);
    cudaGetSymbolAddress((void**)&v,   g_v);
    cudaGetSymbolAddress((void**)&mid, g_mid);
    cudaGetSymbolAddress((void**)&ckv, g_ckv);
    cudaGetSymbolAddress((void**)&cks, g_cks);

    embed_kernel<<<(BG_ * D_) / 256, 256>>>(x, gene_emb, inv_freq, h);

    for (int l = 0; l < L_; l++) {
        const size_t wOff  = (size_t)l * D_ * D_;
        const size_t bOff  = (size_t)l * D_;
        const size_t uOff  = (size_t)l * D_ * FFN_;
        const size_t ubOff = (size_t)l * FFN_;
        const size_t vOff  = (size_t)l * FFN_ * D_;

        ln_kernel<<<BG_ / 8, 256>>>(h, ln1_g + bOff, ln1_b + bOff, hn);

        sgemm_kernel<1><<<dim3(D_ / 128, BG_ / 128), 256>>>(hn, Wq + wOff, bq + bOff, q, BG_, D_, D_);
        sgemm_kernel<1><<<dim3(D_ / 128, BG_ / 128), 256>>>(hn, Wk + wOff, bk + bOff, k, BG_, D_, D_);
        sgemm_kernel<0><<<dim3(D_ / 128, BG_ / 128), 256>>>(hn, Wv + wOff, bv + bOff, v, BG_, D_, D_);

        attn_p1<<<BH_ * NC_, 256>>>(k, v, ckv, cks);
        attn_p2<<<BH_, 1024>>>(ckv, cks);
        attn_p3<<<BH_ * NC_, 256>>>(q, k, v, ckv, cks, h);

        ln_kernel<<<BG_ / 8, 256>>>(h, ln2_g + bOff, ln2_b + bOff, hn);

        sgemm_kernel<2><<<dim3(FFN_ / 128, BG_ / 128), 256>>>(hn, WU + uOff, bU + ubOff, mid, BG_, FFN_, D_);
        sgemm_kernel<3><<<dim3(D_ / 128, BG_ / 128), 256>>>(mid, WV + vOff, bV + bOff, h, BG_, D_, FFN_);
    }

    out_kernel<<<BG_ / 8, 256>>>(h, Wout, bout, out);
}

// round 3
// speedup vs baseline: 2.0819x; 2.0819x over previous
#include <cuda_runtime.h>
#include <cuda_bf16.h>
#include <math.h>
#include <stdint.h>

#define B_   16
#define G_   2048
#define D_   256
#define H_   8
#define DH_  32
#define FFN_ 1024
#define L_   4
#define CH_  64
#define NC_  (G_ / CH_)           // 32 chunks
#define BG_  (B_ * G_)            // 32768 rows
#define BH_  (B_ * H_)            // 128

// ---------------- scratch (device globals; no runtime allocation) ----------
__device__ float g_h[(size_t)BG_ * D_];
__device__ float g_hn[(size_t)BG_ * D_];
__device__ float g_q[(size_t)BG_ * D_];
__device__ float g_k[(size_t)BG_ * D_];
__device__ float g_v[(size_t)BG_ * D_];
__device__ float g_mid[(size_t)BG_ * FFN_];
__device__ float g_ckv[(size_t)BH_ * NC_ * DH_ * DH_];
__device__ float g_cks[(size_t)BH_ * NC_ * DH_];
// transposed weights ([N,K] K-major => B col-major for mma.sync .col)
__device__ float g_WqT[(size_t)L_ * D_ * D_];
__device__ float g_WkT[(size_t)L_ * D_ * D_];
__device__ float g_WvT[(size_t)L_ * D_ * D_];
__device__ float g_WUT[(size_t)L_ * D_ * FFN_];
__device__ float g_WVT[(size_t)L_ * FFN_ * D_];

// ========================= helpers =========================================
__device__ __forceinline__ uint32_t smem_u32(const void* p) {
    uint32_t a;
    asm("{ .reg .u64 t; cvta.to.shared.u64 t, %1; cvt.u32.u64 %0, t; }" : "=r"(a) : "l"(p));
    return a;
}
#define CP_ASYNC16(dst, src) \
    asm volatile("cp.async.cg.shared.global [%0], [%1], 16;" :: "r"(dst), "l"(src))
#define CP_COMMIT() asm volatile("cp.async.commit_group;" ::: "memory")
#define CP_WAIT0()  asm volatile("cp.async.wait_group 0;" ::: "memory")

#define MMA_TF32(c, a, b) \
    asm volatile("mma.sync.aligned.m16n8k8.row.col.f32.tf32.tf32.f32 " \
        "{%0,%1,%2,%3}, {%4,%5,%6,%7}, {%8,%9}, {%0,%1,%2,%3};" \
        : "+f"((c)[0]), "+f"((c)[1]), "+f"((c)[2]), "+f"((c)[3]) \
        : "r"((a)[0]), "r"((a)[1]), "r"((a)[2]), "r"((a)[3]), \
          "r"((b)[0]), "r"((b)[1]))

// ========================= tf32 mma.sync GEMM ==============================
// C[M,N] = A[M,K] @ B[K,N], Bt given as [N,K].
// CTA tile 128x128, K-tile 32, 8 warps (4m x 2n), warp tile 32x64.
// EPI: 0 = +bias, 1 = (x+bias)^2, 2 = gelu_exact(x+bias), 3 = C += x+bias
#define LDA_   36                         // floats per smem row (32 + 4 pad)
#define TILEF_ (128 * LDA_)               // floats per tile (A or B)
#define STGF_  (2 * TILEF_)               // floats per stage (A + B)
#define GSMEM_ (2 * STGF_ * 4)            // 73728 bytes (2 stages)

__device__ __forceinline__ void g_load_tile(const float* __restrict__ A,
                                            const float* __restrict__ Bt,
                                            int m0, int n0, int K, int kt,
                                            uint32_t su, int stage, int tid) {
    const float* Ag = A  + (size_t)m0 * K + kt * 32;
    const float* Bg = Bt + (size_t)n0 * K + kt * 32;
    uint32_t as = su + stage * (STGF_ * 4);
    uint32_t bs = as + TILEF_ * 4;
#pragma unroll
    for (int i = 0; i < 4; i++) {
        int c = tid + (i << 8);           // 0..1023
        int row = c >> 3, c16 = c & 7;    // 128 rows x 8 x 16B
        uint32_t off = row * (LDA_ * 4) + (c16 << 4);
        const float* asrc = Ag + (size_t)row * K + (c16 << 2);
        const float* bsrc = Bg + (size_t)row * K + (c16 << 2);
        CP_ASYNC16(as + off, asrc);
        CP_ASYNC16(bs + off, bsrc);
    }
    CP_COMMIT();
}

template <int EPI>
__global__ __launch_bounds__(256)
void gemm_mma(const float* __restrict__ A, const float* __restrict__ Bt,
              const float* __restrict__ bias, float* __restrict__ C,
              int M, int N, int K) {
    extern __shared__ float sm[];
    uint32_t su = smem_u32(sm);
    const int tid = threadIdx.x, lane = tid & 31, warp = tid >> 5;
    const int m0 = blockIdx.y * 128, n0 = blockIdx.x * 128;
    const int wm = (warp >> 1) * 32, wn = (warp & 1) * 64;
    const int lg = lane >> 2, l4 = lane & 3;
    const int T = K / 32;

    float acc[2][8][4];
#pragma unroll
    for (int mt = 0; mt < 2; mt++)
#pragma unroll
        for (int nt = 0; nt < 8; nt++)
#pragma unroll
            for (int e = 0; e < 4; e++) acc[mt][nt][e] = 0.f;

    g_load_tile(A, Bt, m0, n0, K, 0, su, 0, tid);

    for (int kt = 0; kt < T; kt++) {
        CP_WAIT0();
        __syncthreads();
        if (kt + 1 < T) g_load_tile(A, Bt, m0, n0, K, kt + 1, su, (kt + 1) & 1, tid);

        const float* Aw = sm + (kt & 1) * STGF_;
        const float* Bw = Aw + TILEF_;
#pragma unroll
        for (int kk = 0; kk < 4; kk++) {
            uint32_t a[2][4], b[8][2];
            int kc = kk * 8 + l4;
#pragma unroll
            for (int mt = 0; mt < 2; mt++) {
                int mr = wm + mt * 16 + lg;
                a[mt][0] = __float_as_uint(Aw[mr * LDA_ + kc]);
                a[mt][1] = __float_as_uint(Aw[(mr + 8) * LDA_ + kc]);
                a[mt][2] = __float_as_uint(Aw[mr * LDA_ + kc + 4]);
                a[mt][3] = __float_as_uint(Aw[(mr + 8) * LDA_ + kc + 4]);
            }
#pragma unroll
            for (int nt = 0; nt < 8; nt++) {
                int nr = wn + nt * 8 + lg;
                b[nt][0] = __float_as_uint(Bw[nr * LDA_ + kc]);
                b[nt][1] = __float_as_uint(Bw[nr * LDA_ + kc + 4]);
            }
#pragma unroll
            for (int mt = 0; mt < 2; mt++)
#pragma unroll
                for (int nt = 0; nt < 8; nt++)
                    MMA_TF32(acc[mt][nt], a[mt], b[nt]);
        }
        __syncthreads();
    }

    // epilogue
#pragma unroll
    for (int mt = 0; mt < 2; mt++) {
#pragma unroll
        for (int nt = 0; nt < 8; nt++) {
            int row = m0 + wm + mt * 16 + lg;
            int col = n0 + wn + nt * 8 + l4 * 2;
            float b0 = __ldg(bias + col), b1 = __ldg(bias + col + 1);
#pragma unroll
            for (int half = 0; half < 2; half++) {
                int r = row + half * 8;
                float v0 = acc[mt][nt][half * 2 + 0] + b0;
                float v1 = acc[mt][nt][half * 2 + 1] + b1;
                if (EPI == 1) { v0 = v0 * v0; v1 = v1 * v1; }
                else if (EPI == 2) {
                    v0 = 0.5f * v0 * (1.0f + erff(v0 * 0.70710678118654752f));
                    v1 = 0.5f * v1 * (1.0f + erff(v1 * 0.70710678118654752f));
                }
                float2* p = (float2*)(C + (size_t)r * N + col);
                if (EPI == 3) {
                    float2 o = *p;
                    o.x += v0; o.y += v1;
                    *p = o;
                } else {
                    *p = make_float2(v0, v1);
                }
            }
        }
    }
}

// ---------------- weight transpose: out[n*K+k] = in[k*N+n] ------------------
__global__ void transpose_kernel(const float* __restrict__ in, float* __restrict__ out,
                                 int Kdim, int Ndim) {
    __shared__ float t[32][33];
    int k0 = blockIdx.y * 32, n0 = blockIdx.x * 32;
    int tx = threadIdx.x, ty = threadIdx.y;   // 32 x 8
#pragma unroll
    for (int i = ty; i < 32; i += 8)
        t[i][tx] = in[(size_t)(k0 + i) * Ndim + n0 + tx];
    __syncthreads();
#pragma unroll
    for (int i = ty; i < 32; i += 8)
        out[(size_t)(n0 + i) * Kdim + k0 + tx] = t[tx][i];
}

// ---------------- embedding: h = gene_emb + REE(x) -------------------------
__global__ void embed_kernel(const float* __restrict__ x,
                             const float* __restrict__ ge,
                             const float* __restrict__ invf,
                             float* __restrict__ h) {
    size_t idx = (size_t)blockIdx.x * 256 + threadIdx.x;
    int d = (int)(idx & (D_ - 1));
    size_t bg = idx >> 8;
    int g = (int)(bg & (G_ - 1));
    float xv = x[bg];
    float e;
    if (d < D_ / 2) e = sinf(xv * invf[d]);
    else            e = cosf(xv * invf[d - D_ / 2]);
    if (xv == -10.0f) e = 0.0f;
    h[idx] = ge[(size_t)g * D_ + d] + e;
}

// ---------------- layernorm (warp per row, D=256) ---------------------------
__global__ void ln_kernel(const float* __restrict__ x,
                          const float* __restrict__ gam,
                          const float* __restrict__ bet,
                          float* __restrict__ out) {
    int warp = threadIdx.x >> 5, lane = threadIdx.x & 31;
    int row = blockIdx.x * 8 + warp;
    const float* xr = x + (size_t)row * D_;
    float vals[8];
    float s = 0.f;
#pragma unroll
    for (int i = 0; i < 8; i++) { vals[i] = xr[lane + i * 32]; s += vals[i]; }
#pragma unroll
    for (int o = 16; o; o >>= 1) s += __shfl_xor_sync(0xffffffffu, s, o);
    float mean = s * (1.0f / D_);
    float vs = 0.f;
#pragma unroll
    for (int i = 0; i < 8; i++) { float dlt = vals[i] - mean; vs += dlt * dlt; }
#pragma unroll
    for (int o = 16; o; o >>= 1) vs += __shfl_xor_sync(0xffffffffu, vs, o);
    float rstd = rsqrtf(vs * (1.0f / D_) + 1e-5f);
    float* orow = out + (size_t)row * D_;
#pragma unroll
    for (int i = 0; i < 8; i++) {
        int c = lane + i * 32;
        orow[c] = (vals[i] - mean) * rstd * gam[c] + bet[c];
    }
}

// ---------------- attention phase 1: per-chunk K^T V and sum(k) -------------
__global__ void attn_p1(const float* __restrict__ k, const float* __restrict__ v,
                        float* __restrict__ ckv, float* __restrict__ cks) {
    __shared__ float Ks[CH_][33], Vs[CH_][33];
    int blk = blockIdx.x;
    int c = blk & (NC_ - 1);
    int bh = blk >> 5;
    int b = bh / H_, hh = bh % H_;
    int t = threadIdx.x;
    size_t base = ((size_t)(b * G_ + c * CH_)) * D_ + hh * DH_;
    for (int e = t; e < CH_ * DH_; e += 256) {
        int i = e >> 5, d = e & 31;
        size_t gi = base + (size_t)i * D_ + d;
        Ks[i][d] = k[gi];
        Vs[i][d] = v[gi];
    }
    __syncthreads();
    for (int e = t; e < DH_ * DH_; e += 256) {
        int f = e >> 5, d = e & 31;
        float s = 0.f;
#pragma unroll
        for (int i = 0; i < CH_; i++) s = fmaf(Ks[i][f], Vs[i][d], s);
        ckv[(size_t)blk * (DH_ * DH_) + e] = s;
    }
    if (t < DH_) {
        float s = 0.f;
#pragma unroll
        for (int i = 0; i < CH_; i++) s += Ks[i][t];
        cks[(size_t)blk * DH_ + t] = s;
    }
}

// ---------------- attention phase 2: exclusive prefix across chunks ---------
__global__ void attn_p2(float* __restrict__ ckv, float* __restrict__ cks) {
    int bh = blockIdx.x;
    int t = threadIdx.x;   // 1024 threads
    float run = 0.f;
    for (int c = 0; c < NC_; c++) {
        size_t idx = ((size_t)(bh * NC_ + c)) * (DH_ * DH_) + t;
        float tmp = ckv[idx];
        ckv[idx] = run;
        run += tmp;
    }
    if (t < DH_) {
        float r2 = 0.f;
        for (int c = 0; c < NC_; c++) {
            size_t idx = ((size_t)(bh * NC_ + c)) * DH_ + t;
            float tmp = cks[idx];
            cks[idx] = r2;
            r2 += tmp;
        }
    }
}

// ---------------- attention phase 3: output + residual add into h -----------
__global__ void attn_p3(const float* __restrict__ q, const float* __restrict__ k,
                        const float* __restrict__ v,
                        const float* __restrict__ ckv, const float* __restrict__ cks,
                        float* __restrict__ h) {
    __shared__ float Qs[CH_][33], Ks[CH_][33], Vs[CH_][33];
    __shared__ float S[DH_][33];
    __shared__ float A[CH_][65];
    __shared__ float den[CH_], zz[DH_];
    int blk = blockIdx.x;
    int c = blk & (NC_ - 1);
    int bh = blk >> 5;
    int b = bh / H_, hh = bh % H_;
    int t = threadIdx.x;
    size_t base = ((size_t)(b * G_ + c * CH_)) * D_ + hh * DH_;
    for (int e = t; e < CH_ * DH_; e += 256) {
        int i = e >> 5, d = e & 31;
        size_t gi = base + (size_t)i * D_ + d;
        Qs[i][d] = q[gi];
        Ks[i][d] = k[gi];
        Vs[i][d] = v[gi];
    }
    for (int e = t; e < DH_ * DH_; e += 256)
        S[e >> 5][e & 31] = ckv[(size_t)blk * (DH_ * DH_) + e];
    if (t < DH_) zz[t] = cks[(size_t)blk * DH_ + t];
    __syncthreads();

    for (int e = t; e < CH_ * CH_; e += 256) {
        int i = e >> 6, j = e & 63;
        float s = 0.f;
#pragma unroll
        for (int f = 0; f < DH_; f++) s = fmaf(Qs[i][f], Ks[j][f], s);
        A[i][j] = s;
    }
    __syncthreads();

    for (int i = t; i < CH_; i += 256) {
        float s = 0.f;
#pragma unroll
        for (int f = 0; f < DH_; f++) s = fmaf(Qs[i][f], zz[f], s);
        for (int j = 0; j <= i; j++) s += A[i][j];
        den[i] = s;
    }
    __syncthreads();

    for (int e = t; e < CH_ * DH_; e += 256) {
        int i = e >> 5, d = e & 31;
        float s = 0.f;
#pragma unroll
        for (int f = 0; f < DH_; f++) s = fmaf(Qs[i][f], S[f][d], s);
        for (int j = 0; j <= i; j++) s = fmaf(A[i][j], Vs[j][d], s);
        h[base + (size_t)i * D_ + d] += s / (den[i] + 1e-16f);
    }
}

// ---------------- final projection: out = h @ Wout + bout -------------------
__global__ void out_kernel(const float* __restrict__ h, const float* __restrict__ Wout,
                           const float* __restrict__ bout, float* __restrict__ out) {
    int warp = threadIdx.x >> 5, lane = threadIdx.x & 31;
    int row = blockIdx.x * 8 + warp;
    const float* hr = h + (size_t)row * D_;
    float s = 0.f;
#pragma unroll
    for (int i = 0; i < 8; i++) {
        int c = lane + i * 32;
        s = fmaf(hr[c], Wout[c], s);
    }
#pragma unroll
    for (int o = 16; o; o >>= 1) s += __shfl_xor_sync(0xffffffffu, s, o);
    if (lane == 0) out[row] = s + bout[0];
}

// ---------------------------------------------------------------------------
extern "C" void kernel_launch(void* const* d_in, const int* in_sizes, int n_in,
                              void* d_out, int out_size) {
    const float* x        = (const float*)d_in[0];
    const float* gene_emb = (const float*)d_in[1];
    const float* inv_freq = (const float*)d_in[2];
    const float* Wq       = (const float*)d_in[3];
    const float* bq       = (const float*)d_in[4];
    const float* Wk       = (const float*)d_in[5];
    const float* bk       = (const float*)d_in[6];
    const float* Wv       = (const float*)d_in[7];
    const float* bv       = (const float*)d_in[8];
    const float* ln1_g    = (const float*)d_in[9];
    const float* ln1_b    = (const float*)d_in[10];
    const float* ln2_g    = (const float*)d_in[11];
    const float* ln2_b    = (const float*)d_in[12];
    const float* WU       = (const float*)d_in[13];
    const float* bU       = (const float*)d_in[14];
    const float* WV       = (const float*)d_in[15];
    const float* bV       = (const float*)d_in[16];
    const float* Wout     = (const float*)d_in[17];
    const float* bout     = (const float*)d_in[18];
    float* out = (float*)d_out;

    float *h, *hn, *q, *k, *v, *mid, *ckv, *cks;
    float *WqT, *WkT, *WvT, *WUT, *WVT;
    cudaGetSymbolAddress((void**)&h,   g_h);
    cudaGetSymbolAddress((void**)&hn,  g_hn);
    cudaGetSymbolAddress((void**)&q,   g_q);
    cudaGetSymbolAddress((void**)&k,   g_k);
    cudaGetSymbolAddress((void**)&v,   g_v);
    cudaGetSymbolAddress((void**)&mid, g_mid);
    cudaGetSymbolAddress((void**)&ckv, g_ckv);
    cudaGetSymbolAddress((void**)&cks, g_cks);
    cudaGetSymbolAddress((void**)&WqT, g_WqT);
    cudaGetSymbolAddress((void**)&WkT, g_WkT);
    cudaGetSymbolAddress((void**)&WvT, g_WvT);
    cudaGetSymbolAddress((void**)&WUT, g_WUT);
    cudaGetSymbolAddress((void**)&WVT, g_WVT);

    cudaFuncSetAttribute(gemm_mma<0>, cudaFuncAttributeMaxDynamicSharedMemorySize, GSMEM_);
    cudaFuncSetAttribute(gemm_mma<1>, cudaFuncAttributeMaxDynamicSharedMemorySize, GSMEM_);
    cudaFuncSetAttribute(gemm_mma<2>, cudaFuncAttributeMaxDynamicSharedMemorySize, GSMEM_);
    cudaFuncSetAttribute(gemm_mma<3>, cudaFuncAttributeMaxDynamicSharedMemorySize, GSMEM_);

    // transpose all weights into [N,K] scratch
    {
        dim3 tb(32, 8);
        for (int l = 0; l < L_; l++) {
            transpose_kernel<<<dim3(D_ / 32, D_ / 32), tb>>>(Wq + (size_t)l * D_ * D_, WqT + (size_t)l * D_ * D_, D_, D_);
            transpose_kernel<<<dim3(D_ / 32, D_ / 32), tb>>>(Wk + (size_t)l * D_ * D_, WkT + (size_t)l * D_ * D_, D_, D_);
            transpose_kernel<<<dim3(D_ / 32, D_ / 32), tb>>>(Wv + (size_t)l * D_ * D_, WvT + (size_t)l * D_ * D_, D_, D_);
            transpose_kernel<<<dim3(FFN_ / 32, D_ / 32), tb>>>(WU + (size_t)l * D_ * FFN_, WUT + (size_t)l * D_ * FFN_, D_, FFN_);
            transpose_kernel<<<dim3(D_ / 32, FFN_ / 32), tb>>>(WV + (size_t)l * FFN_ * D_, WVT + (size_t)l * FFN_ * D_, FFN_, D_);
        }
    }

    embed_kernel<<<(BG_ * D_) / 256, 256>>>(x, gene_emb, inv_freq, h);

    for (int l = 0; l < L_; l++) {
        const size_t wOff  = (size_t)l * D_ * D_;
        const size_t bOff  = (size_t)l * D_;
        const size_t uOff  = (size_t)l * D_ * FFN_;
        const size_t ubOff = (size_t)l * FFN_;
        const size_t vOff  = (size_t)l * FFN_ * D_;

        ln_kernel<<<BG_ / 8, 256>>>(h, ln1_g + bOff, ln1_b + bOff, hn);

        gemm_mma<1><<<dim3(D_ / 128, BG_ / 128), 256, GSMEM_>>>(hn, WqT + wOff, bq + bOff, q, BG_, D_, D_);
        gemm_mma<1><<<dim3(D_ / 128, BG_ / 128), 256, GSMEM_>>>(hn, WkT + wOff, bk + bOff, k, BG_, D_, D_);
        gemm_mma<0><<<dim3(D_ / 128, BG_ / 128), 256, GSMEM_>>>(hn, WvT + wOff, bv + bOff, v, BG_, D_, D_);

        attn_p1<<<BH_ * NC_, 256>>>(k, v, ckv, cks);
        attn_p2<<<BH_, 1024>>>(ckv, cks);
        attn_p3<<<BH_ * NC_, 256>>>(q, k, v, ckv, cks, h);

        ln_kernel<<<BG_ / 8, 256>>>(h, ln2_g + bOff, ln2_b + bOff, hn);

        gemm_mma<2><<<dim3(FFN_ / 128, BG_ / 128), 256, GSMEM_>>>(hn, WUT + uOff, bU + ubOff, mid, BG_, FFN_, D_);
        gemm_mma<3><<<dim3(D_ / 128, BG_ / 128), 256, GSMEM_>>>(mid, WVT + vOff, bV + bOff, h, BG_, FFN_ == 0 ? D_ : D_, FFN_);
    }

    out_kernel<<<BG_ / 8, 256>>>(h, Wout, bout, out);
}

// round 4
// speedup vs baseline: 2.3796x; 1.1430x over previous
#include <cuda_runtime.h>
#include <cuda_bf16.h>
#include <math.h>
#include <stdint.h>

#define B_   16
#define G_   2048
#define D_   256
#define H_   8
#define DH_  32
#define FFN_ 1024
#define L_   4
#define CH_  64
#define NC_  (G_ / CH_)           // 32 chunks
#define BG_  (B_ * G_)            // 32768 rows
#define BH_  (B_ * H_)            // 128

// ---------------- scratch (device globals; no runtime allocation) ----------
__device__ float g_h[(size_t)BG_ * D_];
__device__ float g_hn[(size_t)BG_ * D_];
__device__ float g_q[(size_t)BG_ * D_];
__device__ float g_k[(size_t)BG_ * D_];
__device__ float g_v[(size_t)BG_ * D_];
__device__ float g_mid[(size_t)BG_ * FFN_];
__device__ float g_ckv[(size_t)BH_ * NC_ * DH_ * DH_];
__device__ float g_cks[(size_t)BH_ * NC_ * DH_];

// ========================= helpers =========================================
__device__ __forceinline__ uint32_t smem_u32(const void* p) {
    uint32_t a;
    asm("{ .reg .u64 t; cvta.to.shared.u64 t, %1; cvt.u32.u64 %0, t; }" : "=r"(a) : "l"(p));
    return a;
}
#define CP_ASYNC16(dst, src) \
    asm volatile("cp.async.cg.shared.global [%0], [%1], 16;" :: "r"(dst), "l"(src))
#define CP_COMMIT() asm volatile("cp.async.commit_group;" ::: "memory")
#define CP_WAIT0()  asm volatile("cp.async.wait_group 0;" ::: "memory")
#define CP_WAIT1()  asm volatile("cp.async.wait_group 1;" ::: "memory")

#define MMA_TF32(c, a, b) \
    asm volatile("mma.sync.aligned.m16n8k8.row.col.f32.tf32.tf32.f32 " \
        "{%0,%1,%2,%3}, {%4,%5,%6,%7}, {%8,%9}, {%0,%1,%2,%3};" \
        : "+f"((c)[0]), "+f"((c)[1]), "+f"((c)[2]), "+f"((c)[3]) \
        : "r"((a)[0]), "r"((a)[1]), "r"((a)[2]), "r"((a)[3]), \
          "r"((b)[0]), "r"((b)[1]))

// ========================= tf32 mma.sync GEMM ==============================
// C[M,N] = A[M,K] @ B[K,N], B given row-major [K,N] (native weight layout).
// CTA tile 128x128, K-tile 32, 8 warps (4m x 2n), warp tile 32x64.
// 3-stage cp.async pipeline (2-tile lookahead).
#define ALD_   36                          // A smem row stride (floats)
#define BLD_   136                         // B smem row stride (floats)
#define ATILEF_ (128 * ALD_)               // 4608 floats
#define BTILEF_ (32 * BLD_)                // 4352 floats
#define STGF_   (ATILEF_ + BTILEF_)        // 8960 floats per stage
#define NSTG_   3
#define GSMEM_  (NSTG_ * STGF_ * 4)        // 107520 bytes

__device__ __forceinline__ void g_load_tile(const float* __restrict__ A,
                                            const float* __restrict__ Bw,
                                            int m0, int n0, int N, int K, int kt,
                                            uint32_t su, int stage, int tid) {
    const float* Ag = A  + (size_t)m0 * K + kt * 32;
    const float* Bg = Bw + (size_t)(kt * 32) * N + n0;
    uint32_t as = su + stage * (STGF_ * 4);
    uint32_t bs = as + ATILEF_ * 4;
    // A: 128 rows x 32 floats = 1024 x 16B chunks
#pragma unroll
    for (int i = 0; i < 4; i++) {
        int c = tid + (i << 8);
        int row = c >> 3, c16 = c & 7;
        CP_ASYNC16(as + row * (ALD_ * 4) + (c16 << 4),
                   Ag + (size_t)row * K + (c16 << 2));
    }
    // B: 32 rows x 128 floats = 1024 x 16B chunks
#pragma unroll
    for (int i = 0; i < 4; i++) {
        int c = tid + (i << 8);
        int row = c >> 5, c32 = c & 31;
        CP_ASYNC16(bs + row * (BLD_ * 4) + (c32 << 4),
                   Bg + (size_t)row * N + (c32 << 2));
    }
    CP_COMMIT();
}

// mainloop body shared by both GEMM kernels
#define GEMM_MAINLOOP(A_, B_ptr_, N_, K_)                                        \
    const int T = (K_) / 32;                                                     \
    g_load_tile(A_, B_ptr_, m0, n0, N_, K_, 0, su, 0, tid);                      \
    if (T > 1) g_load_tile(A_, B_ptr_, m0, n0, N_, K_, 1, su, 1, tid);           \
    for (int kt = 0; kt < T; kt++) {                                             \
        if (kt + 2 < T) CP_WAIT1(); else CP_WAIT0();                             \
        __syncthreads();                                                         \
        if (kt + 2 < T)                                                          \
            g_load_tile(A_, B_ptr_, m0, n0, N_, K_, kt + 2, su, (kt + 2) % NSTG_, tid); \
        const float* Aw = sm + (kt % NSTG_) * STGF_;                             \
        const float* Bs = Aw + ATILEF_;                                          \
        _Pragma("unroll")                                                        \
        for (int kk = 0; kk < 4; kk++) {                                         \
            uint32_t a[2][4], b[8][2];                                           \
            int kc = kk * 8 + l4;                                                \
            _Pragma("unroll")                                                    \
            for (int mt = 0; mt < 2; mt++) {                                     \
                int mr = wm + mt * 16 + lg;                                      \
                a[mt][0] = __float_as_uint(Aw[mr * ALD_ + kc]);                  \
                a[mt][1] = __float_as_uint(Aw[(mr + 8) * ALD_ + kc]);            \
                a[mt][2] = __float_as_uint(Aw[mr * ALD_ + kc + 4]);              \
                a[mt][3] = __float_as_uint(Aw[(mr + 8) * ALD_ + kc + 4]);        \
            }                                                                    \
            _Pragma("unroll")                                                    \
            for (int nt = 0; nt < 8; nt++) {                                     \
                int nr = wn + nt * 8 + lg;                                       \
                b[nt][0] = __float_as_uint(Bs[kc * BLD_ + nr]);                  \
                b[nt][1] = __float_as_uint(Bs[(kc + 4) * BLD_ + nr]);            \
            }                                                                    \
            _Pragma("unroll")                                                    \
            for (int mt = 0; mt < 2; mt++)                                       \
                _Pragma("unroll")                                                \
                for (int nt = 0; nt < 8; nt++)                                   \
                    MMA_TF32(acc[mt][nt], a[mt], b[nt]);                         \
        }                                                                        \
        __syncthreads();                                                         \
    }

// Generic GEMM.  EPI: 0 = +bias, 2 = gelu_exact(x+bias), 3 = C += x+bias
template <int EPI>
__global__ __launch_bounds__(256)
void gemm_mma(const float* __restrict__ A, const float* __restrict__ Bw,
              const float* __restrict__ bias, float* __restrict__ C,
              int M, int N, int K) {
    extern __shared__ float sm[];
    uint32_t su = smem_u32(sm);
    const int tid = threadIdx.x, lane = tid & 31, warp = tid >> 5;
    const int m0 = blockIdx.y * 128, n0 = blockIdx.x * 128;
    const int wm = (warp >> 1) * 32, wn = (warp & 1) * 64;
    const int lg = lane >> 2, l4 = lane & 3;

    float acc[2][8][4];
#pragma unroll
    for (int mt = 0; mt < 2; mt++)
#pragma unroll
        for (int nt = 0; nt < 8; nt++)
#pragma unroll
            for (int e = 0; e < 4; e++) acc[mt][nt][e] = 0.f;

    GEMM_MAINLOOP(A, Bw, N, K)

#pragma unroll
    for (int mt = 0; mt < 2; mt++) {
#pragma unroll
        for (int nt = 0; nt < 8; nt++) {
            int row = m0 + wm + mt * 16 + lg;
            int col = n0 + wn + nt * 8 + l4 * 2;
            float b0 = __ldg(bias + col), b1 = __ldg(bias + col + 1);
#pragma unroll
            for (int half = 0; half < 2; half++) {
                int r = row + half * 8;
                float v0 = acc[mt][nt][half * 2 + 0] + b0;
                float v1 = acc[mt][nt][half * 2 + 1] + b1;
                if (EPI == 2) {
                    v0 = 0.5f * v0 * (1.0f + erff(v0 * 0.70710678118654752f));
                    v1 = 0.5f * v1 * (1.0f + erff(v1 * 0.70710678118654752f));
                }
                float2* p = (float2*)(C + (size_t)r * N + col);
                if (EPI == 3) {
                    float2 o = *p;
                    o.x += v0; o.y += v1;
                    *p = o;
                } else {
                    *p = make_float2(v0, v1);
                }
            }
        }
    }
}

// Fused QKV GEMM: grid.x = 6 (2 n-blocks x {q,k,v}); square epilogue for q,k.
__global__ __launch_bounds__(256)
void qkv_gemm(const float* __restrict__ A,
              const float* __restrict__ Wq, const float* __restrict__ Wk,
              const float* __restrict__ Wv,
              const float* __restrict__ bq, const float* __restrict__ bk,
              const float* __restrict__ bv,
              float* __restrict__ Q, float* __restrict__ Ko, float* __restrict__ V) {
    extern __shared__ float sm[];
    uint32_t su = smem_u32(sm);
    const int tid = threadIdx.x, lane = tid & 31, warp = tid >> 5;
    const int which = blockIdx.x >> 1;
    const int m0 = blockIdx.y * 128, n0 = (blockIdx.x & 1) * 128;
    const int wm = (warp >> 1) * 32, wn = (warp & 1) * 64;
    const int lg = lane >> 2, l4 = lane & 3;
    const int N = D_, K = D_;

    const float* Bw  = (which == 0) ? Wq : (which == 1) ? Wk : Wv;
    const float* bias = (which == 0) ? bq : (which == 1) ? bk : bv;
    float* C = (which == 0) ? Q : (which == 1) ? Ko : V;
    const bool sq = (which < 2);

    float acc[2][8][4];
#pragma unroll
    for (int mt = 0; mt < 2; mt++)
#pragma unroll
        for (int nt = 0; nt < 8; nt++)
#pragma unroll
            for (int e = 0; e < 4; e++) acc[mt][nt][e] = 0.f;

    GEMM_MAINLOOP(A, Bw, N, K)

#pragma unroll
    for (int mt = 0; mt < 2; mt++) {
#pragma unroll
        for (int nt = 0; nt < 8; nt++) {
            int row = m0 + wm + mt * 16 + lg;
            int col = n0 + wn + nt * 8 + l4 * 2;
            float b0 = __ldg(bias + col), b1 = __ldg(bias + col + 1);
#pragma unroll
            for (int half = 0; half < 2; half++) {
                int r = row + half * 8;
                float v0 = acc[mt][nt][half * 2 + 0] + b0;
                float v1 = acc[mt][nt][half * 2 + 1] + b1;
                if (sq) { v0 = v0 * v0; v1 = v1 * v1; }
                *(float2*)(C + (size_t)r * N + col) = make_float2(v0, v1);
            }
        }
    }
}

// ---------------- embedding: h = gene_emb + REE(x) -------------------------
__global__ void embed_kernel(const float* __restrict__ x,
                             const float* __restrict__ ge,
                             const float* __restrict__ invf,
                             float* __restrict__ h) {
    size_t idx = (size_t)blockIdx.x * 256 + threadIdx.x;
    int d = (int)(idx & (D_ - 1));
    size_t bg = idx >> 8;
    int g = (int)(bg & (G_ - 1));
    float xv = x[bg];
    float e;
    if (d < D_ / 2) e = sinf(xv * invf[d]);
    else            e = cosf(xv * invf[d - D_ / 2]);
    if (xv == -10.0f) e = 0.0f;
    h[idx] = ge[(size_t)g * D_ + d] + e;
}

// ---------------- layernorm (warp per row, D=256) ---------------------------
__global__ void ln_kernel(const float* __restrict__ x,
                          const float* __restrict__ gam,
                          const float* __restrict__ bet,
                          float* __restrict__ out) {
    int warp = threadIdx.x >> 5, lane = threadIdx.x & 31;
    int row = blockIdx.x * 8 + warp;
    const float* xr = x + (size_t)row * D_;
    float vals[8];
    float s = 0.f;
#pragma unroll
    for (int i = 0; i < 8; i++) { vals[i] = xr[lane + i * 32]; s += vals[i]; }
#pragma unroll
    for (int o = 16; o; o >>= 1) s += __shfl_xor_sync(0xffffffffu, s, o);
    float mean = s * (1.0f / D_);
    float vs = 0.f;
#pragma unroll
    for (int i = 0; i < 8; i++) { float dlt = vals[i] - mean; vs += dlt * dlt; }
#pragma unroll
    for (int o = 16; o; o >>= 1) vs += __shfl_xor_sync(0xffffffffu, vs, o);
    float rstd = rsqrtf(vs * (1.0f / D_) + 1e-5f);
    float* orow = out + (size_t)row * D_;
#pragma unroll
    for (int i = 0; i < 8; i++) {
        int c = lane + i * 32;
        orow[c] = (vals[i] - mean) * rstd * gam[c] + bet[c];
    }
}

// ---------------- attention phase 1: per-chunk K^T V and sum(k) -------------
__global__ void attn_p1(const float* __restrict__ k, const float* __restrict__ v,
                        float* __restrict__ ckv, float* __restrict__ cks) {
    __shared__ float Ks[CH_][33], Vs[CH_][33];
    int blk = blockIdx.x;
    int c = blk & (NC_ - 1);
    int bh = blk >> 5;
    int b = bh / H_, hh = bh % H_;
    int t = threadIdx.x;
    size_t base = ((size_t)(b * G_ + c * CH_)) * D_ + hh * DH_;
    for (int e = t; e < CH_ * DH_; e += 256) {
        int i = e >> 5, d = e & 31;
        size_t gi = base + (size_t)i * D_ + d;
        Ks[i][d] = k[gi];
        Vs[i][d] = v[gi];
    }
    __syncthreads();
    for (int e = t; e < DH_ * DH_; e += 256) {
        int f = e >> 5, d = e & 31;
        float s = 0.f;
#pragma unroll
        for (int i = 0; i < CH_; i++) s = fmaf(Ks[i][f], Vs[i][d], s);
        ckv[(size_t)blk * (DH_ * DH_) + e] = s;
    }
    if (t < DH_) {
        float s = 0.f;
#pragma unroll
        for (int i = 0; i < CH_; i++) s += Ks[i][t];
        cks[(size_t)blk * DH_ + t] = s;
    }
}

// ---------------- attention phase 2: exclusive prefix across chunks ---------
__global__ void attn_p2(float* __restrict__ ckv, float* __restrict__ cks) {
    int bh = blockIdx.x;
    int t = threadIdx.x;   // 1024 threads
    float run = 0.f;
    for (int c = 0; c < NC_; c++) {
        size_t idx = ((size_t)(bh * NC_ + c)) * (DH_ * DH_) + t;
        float tmp = ckv[idx];
        ckv[idx] = run;
        run += tmp;
    }
    if (t < DH_) {
        float r2 = 0.f;
        for (int c = 0; c < NC_; c++) {
            size_t idx = ((size_t)(bh * NC_ + c)) * DH_ + t;
            float tmp = cks[idx];
            cks[idx] = r2;
            r2 += tmp;
        }
    }
}

// ---------------- attention phase 3: output + residual add into h -----------
__global__ void attn_p3(const float* __restrict__ q, const float* __restrict__ k,
                        const float* __restrict__ v,
                        const float* __restrict__ ckv, const float* __restrict__ cks,
                        float* __restrict__ h) {
    __shared__ float Qs[CH_][33], Ks[CH_][33], Vs[CH_][33];
    __shared__ float S[DH_][33];
    __shared__ float A[CH_][65];
    __shared__ float den[CH_], zz[DH_];
    int blk = blockIdx.x;
    int c = blk & (NC_ - 1);
    int bh = blk >> 5;
    int b = bh / H_, hh = bh % H_;
    int t = threadIdx.x;
    size_t base = ((size_t)(b * G_ + c * CH_)) * D_ + hh * DH_;
    for (int e = t; e < CH_ * DH_; e += 256) {
        int i = e >> 5, d = e & 31;
        size_t gi = base + (size_t)i * D_ + d;
        Qs[i][d] = q[gi];
        Ks[i][d] = k[gi];
        Vs[i][d] = v[gi];
    }
    for (int e = t; e < DH_ * DH_; e += 256)
        S[e >> 5][e & 31] = ckv[(size_t)blk * (DH_ * DH_) + e];
    if (t < DH_) zz[t] = cks[(size_t)blk * DH_ + t];
    __syncthreads();

    for (int e = t; e < CH_ * CH_; e += 256) {
        int i = e >> 6, j = e & 63;
        float s = 0.f;
#pragma unroll
        for (int f = 0; f < DH_; f++) s = fmaf(Qs[i][f], Ks[j][f], s);
        A[i][j] = s;
    }
    __syncthreads();

    for (int i = t; i < CH_; i += 256) {
        float s = 0.f;
#pragma unroll
        for (int f = 0; f < DH_; f++) s = fmaf(Qs[i][f], zz[f], s);
        for (int j = 0; j <= i; j++) s += A[i][j];
        den[i] = s;
    }
    __syncthreads();

    for (int e = t; e < CH_ * DH_; e += 256) {
        int i = e >> 5, d = e & 31;
        float s = 0.f;
#pragma unroll
        for (int f = 0; f < DH_; f++) s = fmaf(Qs[i][f], S[f][d], s);
        for (int j = 0; j <= i; j++) s = fmaf(A[i][j], Vs[j][d], s);
        h[base + (size_t)i * D_ + d] += s / (den[i] + 1e-16f);
    }
}

// ---------------- final projection: out = h @ Wout + bout -------------------
__global__ void out_kernel(const float* __restrict__ h, const float* __restrict__ Wout,
                           const float* __restrict__ bout, float* __restrict__ out) {
    int warp = threadIdx.x >> 5, lane = threadIdx.x & 31;
    int row = blockIdx.x * 8 + warp;
    const float* hr = h + (size_t)row * D_;
    float s = 0.f;
#pragma unroll
    for (int i = 0; i < 8; i++) {
        int c = lane + i * 32;
        s = fmaf(hr[c], Wout[c], s);
    }
#pragma unroll
    for (int o = 16; o; o >>= 1) s += __shfl_xor_sync(0xffffffffu, s, o);
    if (lane == 0) out[row] = s + bout[0];
}

// ---------------------------------------------------------------------------
extern "C" void kernel_launch(void* const* d_in, const int* in_sizes, int n_in,
                              void* d_out, int out_size) {
    const float* x        = (const float*)d_in[0];
    const float* gene_emb = (const float*)d_in[1];
    const float* inv_freq = (const float*)d_in[2];
    const float* Wq       = (const float*)d_in[3];
    const float* bq       = (const float*)d_in[4];
    const float* Wk       = (const float*)d_in[5];
    const float* bk       = (const float*)d_in[6];
    const float* Wv       = (const float*)d_in[7];
    const float* bv       = (const float*)d_in[8];
    const float* ln1_g    = (const float*)d_in[9];
    const float* ln1_b    = (const float*)d_in[10];
    const float* ln2_g    = (const float*)d_in[11];
    const float* ln2_b    = (const float*)d_in[12];
    const float* WU       = (const float*)d_in[13];
    const float* bU       = (const float*)d_in[14];
    const float* WV       = (const float*)d_in[15];
    const float* bV       = (const float*)d_in[16];
    const float* Wout     = (const float*)d_in[17];
    const float* bout     = (const float*)d_in[18];
    float* out = (float*)d_out;

    float *h, *hn, *q, *k, *v, *mid, *ckv, *cks;
    cudaGetSymbolAddress((void**)&h,   g_h);
    cudaGetSymbolAddress((void**)&hn,  g_hn);
    cudaGetSymbolAddress((void**)&q,   g_q);
    cudaGetSymbolAddress((void**)&k,   g_k);
    cudaGetSymbolAddress((void**)&v,   g_v);
    cudaGetSymbolAddress((void**)&mid, g_mid);
    cudaGetSymbolAddress((void**)&ckv, g_ckv);
    cudaGetSymbolAddress((void**)&cks, g_cks);

    cudaFuncSetAttribute(qkv_gemm,    cudaFuncAttributeMaxDynamicSharedMemorySize, GSMEM_);
    cudaFuncSetAttribute(gemm_mma<2>, cudaFuncAttributeMaxDynamicSharedMemorySize, GSMEM_);
    cudaFuncSetAttribute(gemm_mma<3>, cudaFuncAttributeMaxDynamicSharedMemorySize, GSMEM_);

    embed_kernel<<<(BG_ * D_) / 256, 256>>>(x, gene_emb, inv_freq, h);

    for (int l = 0; l < L_; l++) {
        const size_t wOff  = (size_t)l * D_ * D_;
        const size_t bOff  = (size_t)l * D_;
        const size_t uOff  = (size_t)l * D_ * FFN_;
        const size_t ubOff = (size_t)l * FFN_;
        const size_t vOff  = (size_t)l * FFN_ * D_;

        ln_kernel<<<BG_ / 8, 256>>>(h, ln1_g + bOff, ln1_b + bOff, hn);

        qkv_gemm<<<dim3(6, BG_ / 128), 256, GSMEM_>>>(
            hn, Wq + wOff, Wk + wOff, Wv + wOff,
            bq + bOff, bk + bOff, bv + bOff, q, k, v);

        attn_p1<<<BH_ * NC_, 256>>>(k, v, ckv, cks);
        attn_p2<<<BH_, 1024>>>(ckv, cks);
        attn_p3<<<BH_ * NC_, 256>>>(q, k, v, ckv, cks, h);

        ln_kernel<<<BG_ / 8, 256>>>(h, ln2_g + bOff, ln2_b + bOff, hn);

        gemm_mma<2><<<dim3(FFN_ / 128, BG_ / 128), 256, GSMEM_>>>(hn, WU + uOff, bU + ubOff, mid, BG_, FFN_, D_);
        gemm_mma<3><<<dim3(D_ / 128, BG_ / 128), 256, GSMEM_>>>(mid, WV + vOff, bV + bOff, h, BG_, D_, FFN_);
    }

    out_kernel<<<BG_ / 8, 256>>>(h, Wout, bout, out);
}